// round 3
// baseline (speedup 1.0000x reference)
#include <cuda_runtime.h>

#define Bq 16
#define Sq 128
#define Dq 300
#define Oq 64
#define Eq 16
#define Tq 45
#define TP 48               // padded type count
#define ROWS_TOT (Bq*Sq)    // 2048
#define WROW (Dq+Eq)        // 316
#define KT 60               // K-chunk
#define NCOLS 256           // unified GEMM cols: [hi 64 | hj 64 | ht 64 | S 48 | pad 16]
#define CPAD 65             // per-column smem stride (conflict-free)

// __device__ scratch (allocation-free rule)
__device__ float g_ht[ROWS_TOT*Oq];
__device__ float g_E [ROWS_TOT*TP];
__device__ float g_U1[Tq*Oq];
__device__ float g_U2[Tq*Oq];
__device__ float g_e [TP];
__device__ float g_Vt[TP*304];     // V transposed: [t][k], k-rowlen 304

// ---------------------------------------------------------------------------
// K0a: U1[t][o], U2[t][o] = dep-type embedding folded through W1/W2 tails,
//      plus e[t] = b1·U2[t] + b2·U1[t] + U1[t]·U2[t].  45 blocks x 64 threads.
// ---------------------------------------------------------------------------
__global__ void u_kernel(const float* __restrict__ dep_table,
                         const float* __restrict__ W1, const float* __restrict__ b1,
                         const float* __restrict__ W2, const float* __restrict__ b2) {
    __shared__ float sdt[Eq];
    __shared__ float swp[2];
    int t = blockIdx.x, o = threadIdx.x;
    if (o < Eq) sdt[o] = dep_table[t*Eq + o];
    __syncthreads();
    float s1 = 0.f, s2 = 0.f;
    #pragma unroll
    for (int e = 0; e < Eq; e++) {
        float de = sdt[e];
        s1 += __ldg(&W1[o*WROW + Dq + e]) * de;
        s2 += __ldg(&W2[o*WROW + Dq + e]) * de;
    }
    g_U1[t*Oq + o] = s1;
    g_U2[t*Oq + o] = s2;
    float v = b1[o]*s2 + b2[o]*s1 + s1*s2;
    #pragma unroll
    for (int off = 16; off; off >>= 1) v += __shfl_xor_sync(0xffffffffu, v, off);
    if ((o & 31) == 0) swp[o >> 5] = v;
    __syncthreads();
    if (o == 0) g_e[t] = swp[0] + swp[1];
}

// ---------------------------------------------------------------------------
// K0b: V[t][k] = sum_o W1[o][k]*U2[t][o] + W2[o][k]*U1[t][o], written
//      transposed to g_Vt[t*304+k].  75 blocks x 192 threads (4 k x 48 t).
// ---------------------------------------------------------------------------
__global__ void __launch_bounds__(192) v_kernel(const float* __restrict__ W1,
                                                const float* __restrict__ W2) {
    __shared__ float sU1t[Oq*49], sU2t[Oq*49];     // [o][t] pad 49
    __shared__ float sW1c[Oq*4], sW2c[Oq*4];       // [o][kk]
    int tid = threadIdx.x;
    int kbase = blockIdx.x * 4;
    for (int i = tid; i < Tq*Oq; i += 192) {
        int t = i >> 6, o = i & 63;
        sU1t[o*49 + t] = g_U1[i];
        sU2t[o*49 + t] = g_U2[i];
    }
    for (int i = tid; i < Oq*4; i += 192) {
        int o = i >> 2, k = i & 3;
        sW1c[i] = __ldg(&W1[o*WROW + kbase + k]);
        sW2c[i] = __ldg(&W2[o*WROW + kbase + k]);
    }
    __syncthreads();
    int t = tid % TP, kk = tid / TP;
    float acc = 0.f;
    if (t < Tq) {
        #pragma unroll 8
        for (int o = 0; o < Oq; o++)
            acc += sW1c[o*4 + kk] * sU2t[o*49 + t]
                 + sW2c[o*4 + kk] * sU1t[o*49 + t];
    }
    g_Vt[t*304 + kbase + kk] = acc;   // 0 for t>=45
}

// ---------------------------------------------------------------------------
// K1: unified GEMM (16 rows x 256 cols, K=300) + score/exp-table epilogue.
//     128 blocks x 256 threads. Thread: 8 rows x 2 cols (cg, cg+128).
// ---------------------------------------------------------------------------
__global__ void __launch_bounds__(256) gemm_kernel(
        const float* __restrict__ h,
        const float* __restrict__ W1, const float* __restrict__ b1,
        const float* __restrict__ W2, const float* __restrict__ b2,
        const float* __restrict__ Wg, const float* __restrict__ bg,
        const unsigned char* __restrict__ mask8) {
    extern __shared__ float sm[];
    float* sh = sm;                 // 16*300 = 4800
    float* sW = sm + 16*Dq;         // NCOLS*CPAD = 16640
    __shared__ int sp[5];
    __shared__ float sw[16];

    int tid  = threadIdx.x;
    int row0 = blockIdx.x * 16;
    int b    = row0 >> 7;

    // ---- aspect span scan (dual bool-dtype robust) ----
    if (tid < 5) sp[tid] = (tid==0 || tid==3) ? Sq : ((tid==1 || tid==4) ? -1 : 0);
    __syncthreads();
    if (tid < 128 && mask8[(b<<7) + tid]) {
        atomicMin(&sp[0], tid); atomicMax(&sp[1], tid); atomicAdd(&sp[2], 1);
    }
    __syncthreads();
    bool valid8 = (sp[2] == 3 && sp[1] - sp[0] == 2);
    if (!valid8) {
        const int* m32 = (const int*)mask8;
        if (tid < 128 && m32[(b<<7) + tid] != 0) {
            atomicMin(&sp[3], tid); atomicMax(&sp[4], tid);
        }
    }
    __syncthreads();
    int st = valid8 ? sp[0] : sp[3];
    int en = valid8 ? sp[1] : sp[4];
    if (tid < 16) {
        int s = (row0 + tid) & 127;
        float w;
        if (s < st)      w = 1.0f - (float)(st - s) * (1.0f/128.0f);
        else if (s > en) w = 1.0f - (float)(s - en) * (1.0f/128.0f);
        else             w = 0.0f;
        sw[tid] = w;
    }
    __syncthreads();

    // ---- stage position-weighted h ----
    {
        const float4* h4 = (const float4*)(h + (size_t)row0 * Dq);
        float4* sh4 = (float4*)sh;
        for (int i = tid; i < 16*75; i += 256) {
            int r = i / 75;
            float4 v = h4[i];
            float w = sw[r];
            v.x *= w; v.y *= w; v.z *= w; v.w *= w;
            sh4[i] = v;
        }
    }

    int cg = tid & 127;
    int rg = tid >> 7;
    float aA[8] = {0,0,0,0,0,0,0,0};
    float aB[8] = {0,0,0,0,0,0,0,0};

    for (int c = 0; c < Dq/KT; c++) {
        __syncthreads();
        // stage W1|W2|Wg column-major [col][k] (pad CPAD)
        for (int i = tid; i < 192*15; i += 256) {
            int om = i / 15, q = i - om*15;
            int m = om >> 6, o = om & 63;
            const float* Wsrc = (m == 0) ? W1 : (m == 1) ? W2 : Wg;
            int rl = (m == 2) ? Dq : WROW;
            float4 v = *(const float4*)(Wsrc + (size_t)o*rl + c*KT + q*4);
            float* dst = sW + om*CPAD + q*4;
            dst[0]=v.x; dst[1]=v.y; dst[2]=v.z; dst[3]=v.w;
        }
        // stage V rows (cols 192..239)
        for (int i = tid; i < TP*15; i += 256) {
            int t = i / 15, q = i - t*15;
            float4 v = *(const float4*)(g_Vt + t*304 + c*KT + q*4);
            float* dst = sW + (192+t)*CPAD + q*4;
            dst[0]=v.x; dst[1]=v.y; dst[2]=v.z; dst[3]=v.w;
        }
        // zero pad cols 240..255
        for (int i = tid; i < 16*KT; i += 256) {
            int cc = i / KT, k = i - cc*KT;
            sW[(240+cc)*CPAD + k] = 0.f;
        }
        __syncthreads();

        const float* wA = sW + cg*CPAD;
        const float* wB = sW + (128+cg)*CPAD;
        const float* shc = sh + c*KT;
        #pragma unroll 3
        for (int k4 = 0; k4 < 15; k4++) {
            float4 hv[8];
            #pragma unroll
            for (int j = 0; j < 8; j++)
                hv[j] = *(const float4*)(shc + (rg*8+j)*Dq + k4*4);
            #pragma unroll
            for (int kk = 0; kk < 4; kk++) {
                float a  = wA[k4*4 + kk];
                float bw = wB[k4*4 + kk];
                #pragma unroll
                for (int j = 0; j < 8; j++) {
                    float hx = ((const float*)&hv[j])[kk];
                    aA[j] += hx * a;
                    aB[j] += hx * bw;
                }
            }
        }
    }
    __syncthreads();

    // ---- epilogue: reuse smem ----
    float* shi = sh;                // 1024
    float* shj = sh + 1024;         // 1024
    float* sc0 = sh + 2048;         // 16
    float* smx = sh + 2064;         // 16
    float* se  = sh + 2080;         // 48
    float* ssv = sW;                // 16*48

    if (tid < Tq) se[tid] = g_e[tid];
    if (cg < 64) {
        float bA = b1[cg], bB = bg[cg];
        #pragma unroll
        for (int j = 0; j < 8; j++) {
            int row = rg*8 + j;
            shi[row*64 + cg] = aA[j] + bA;
            g_ht[(size_t)(row0 + row)*Oq + cg] = aB[j] + bB;
        }
    } else {
        float bA = b2[cg - 64];
        #pragma unroll
        for (int j = 0; j < 8; j++) {
            int row = rg*8 + j;
            shj[row*64 + (cg - 64)] = aA[j] + bA;
        }
    }
    __syncthreads();

    // c0[r] = hi[r]·hj[r]
    if (tid < 128) {
        int r = tid >> 3, p = tid & 7;
        const float* hi = shi + r*64 + p*8;
        const float* hj = shj + r*64 + p*8;
        float s = 0.f;
        #pragma unroll
        for (int q = 0; q < 8; q++) s += hi[q]*hj[q];
        s += __shfl_down_sync(0xffffffffu, s, 4, 8);
        s += __shfl_down_sync(0xffffffffu, s, 2, 8);
        s += __shfl_down_sync(0xffffffffu, s, 1, 8);
        if (p == 0) sc0[r] = s;
    }
    __syncthreads();

    // sval[r][t]
    if (cg >= 64 && cg < 64 + TP) {
        int t = cg - 64;
        float ee = (t < Tq) ? se[t] : 0.f;
        #pragma unroll
        for (int j = 0; j < 8; j++) {
            int row = rg*8 + j;
            ssv[row*TP + t] = (t < Tq) ? (aB[j] + sc0[row] + ee) : -1e30f;
        }
    }
    __syncthreads();
    if (tid < 16) {
        float m = -1e30f;
        #pragma unroll 8
        for (int t = 0; t < TP; t++) m = fmaxf(m, ssv[tid*TP + t]);
        smx[tid] = m;
    }
    __syncthreads();
    for (int i = tid; i < 16*TP; i += 256) {
        int r = i / TP, t = i - r*TP;
        float v = (t > 0 && t < Tq) ? __expf((ssv[i] - smx[r]) * 0.125f) : 0.f;
        g_E[(size_t)(row0 + r)*TP + t] = v;
    }
}

// ---------------------------------------------------------------------------
// K2 (attn): gather e=sE[ty], row-sum, out = (sum_pos e*ht)/(sum+1e-6)+bias.
//     128 blocks x 256 threads, 16 rows/block.
// ---------------------------------------------------------------------------
__global__ void __launch_bounds__(256) attn_kernel(
        const int* __restrict__ dep,
        const float* __restrict__ bias,
        float* __restrict__ out) {
    extern __shared__ float am[];
    float* sE   = am;                 // 16*48  = 768
    float* sht  = am + 768;           // 128*64 = 8192
    float* sA   = am + 768 + 8192;    // 16*128 = 2048
    float* sred = sA + 2048;          // 16*64  = 1024
    float* spart= sred + 1024;        // 16*4
    float* sden = spart + 64;         // 16

    int tid = threadIdx.x;
    int gr0 = blockIdx.x * 16;
    int b   = gr0 >> 7;

    for (int i = tid; i < 16*TP; i += 256) sE[i] = g_E[(size_t)gr0*TP + i];
    {
        const float4* src = (const float4*)(g_ht + (size_t)(b << 7) * Oq);
        float4* dst = (float4*)sht;
        for (int i = tid; i < Sq*Oq/4; i += 256) dst[i] = src[i];
    }
    __syncthreads();

    int pos = tid & 127, rh = tid >> 7;
    int wid = tid >> 5, lane = tid & 31;
    #pragma unroll
    for (int rr = 0; rr < 8; rr++) {
        int row = rr*2 + rh;
        int ty = dep[(size_t)(gr0 + row)*Sq + pos];
        float e = sE[row*TP + ty];
        sA[row*Sq + pos] = e;
        float s = e;
        #pragma unroll
        for (int off = 16; off; off >>= 1)
            s += __shfl_xor_sync(0xffffffffu, s, off);
        if (lane == 0) spart[row*4 + (wid & 3)] = s;
    }
    __syncthreads();
    if (tid < 16) {
        float s = spart[tid*4] + spart[tid*4+1] + spart[tid*4+2] + spart[tid*4+3];
        sden[tid] = 1.0f / (s + 1e-6f);
    }
    __syncthreads();

    // matmul: thread (o2 = tid&31 -> float2 cols, g = tid>>5: rgp=g&3 (4 rows), uh=g>>2)
    int o2 = tid & 31, g = tid >> 5;
    int rgp = g & 3, uh = g >> 2;
    float2 acc[4];
    #pragma unroll
    for (int r = 0; r < 4; r++) acc[r] = make_float2(0.f, 0.f);
    #pragma unroll 4
    for (int u4 = 0; u4 < 16; u4++) {
        int u = uh*64 + u4*4;
        float4 av[4];
        #pragma unroll
        for (int r = 0; r < 4; r++)
            av[r] = *(const float4*)&sA[(rgp*4 + r)*Sq + u];
        #pragma unroll
        for (int kk = 0; kk < 4; kk++) {
            float2 hv = *(const float2*)&sht[(u + kk)*Oq + o2*2];
            #pragma unroll
            for (int r = 0; r < 4; r++) {
                float a = ((const float*)&av[r])[kk];
                acc[r].x += a * hv.x;
                acc[r].y += a * hv.y;
            }
        }
    }
    if (uh == 1) {
        #pragma unroll
        for (int r = 0; r < 4; r++)
            *(float2*)&sred[(rgp*4 + r)*Oq + o2*2] = acc[r];
    }
    __syncthreads();
    if (uh == 0) {
        float2 bb = *(const float2*)&bias[o2*2];
        #pragma unroll
        for (int r = 0; r < 4; r++) {
            int row = rgp*4 + r;
            float2 other = *(const float2*)&sred[row*Oq + o2*2];
            float den = sden[row];
            float ox = (acc[r].x + other.x) * den + bb.x;
            float oy = (acc[r].y + other.y) * den + bb.y;
            float2 res = make_float2(fmaxf(ox, 0.f), fmaxf(oy, 0.f));
            *(float2*)&out[(size_t)(gr0 + row)*Oq + o2*2] = res;
        }
    }
}

// ---------------------------------------------------------------------------
// Inputs: h, dep_table, W1, b1, W2, b2, Wg, bg, bias, dep_type_matrix, aspect_mask
// ---------------------------------------------------------------------------
extern "C" void kernel_launch(void* const* d_in, const int* in_sizes, int n_in,
                              void* d_out, int out_size) {
    const float* h         = (const float*)d_in[0];
    const float* dep_table = (const float*)d_in[1];
    const float* W1        = (const float*)d_in[2];
    const float* b1        = (const float*)d_in[3];
    const float* W2        = (const float*)d_in[4];
    const float* b2        = (const float*)d_in[5];
    const float* Wg        = (const float*)d_in[6];
    const float* bg        = (const float*)d_in[7];
    const float* bias      = (const float*)d_in[8];
    const int*   dep       = (const int*)d_in[9];
    const unsigned char* mask = (const unsigned char*)d_in[10];

    const int gemm_smem = (16*Dq + NCOLS*CPAD) * (int)sizeof(float);   // ~85.8 KB
    const int attn_smem = (768 + 8192 + 2048 + 1024 + 64 + 16 + 16) * (int)sizeof(float);
    cudaFuncSetAttribute(gemm_kernel, cudaFuncAttributeMaxDynamicSharedMemorySize, gemm_smem);
    cudaFuncSetAttribute(attn_kernel, cudaFuncAttributeMaxDynamicSharedMemorySize, attn_smem);

    u_kernel<<<Tq, 64>>>(dep_table, W1, b1, W2, b2);
    v_kernel<<<75, 192>>>(W1, W2);
    gemm_kernel<<<ROWS_TOT/16, 256, gemm_smem>>>(h, W1, b1, W2, b2, Wg, bg, mask);
    attn_kernel<<<ROWS_TOT/16, 256, attn_smem>>>(dep, bias, (float*)d_out);
}